// round 5
// baseline (speedup 1.0000x reference)
#include <cuda_runtime.h>

#define N_NODES   100000
#define EMBED     64
#define HEADS     8
#define HD        8
#define FFN_DIM   256
#define MAX_EDGES 1600000

// ---------------- scratch (device globals; no allocation allowed) ----------------
__device__ float g_q[N_NODES * EMBED];
__device__ float g_k[N_NODES * EMBED];
__device__ float g_v[N_NODES * EMBED];
__device__ float g_xln[N_NODES * EMBED];     // LN1(x + attn)
__device__ float g_hid[N_NODES * FFN_DIM];   // relu(xln@w1+b1)
__device__ float g_f[N_NODES * EMBED];       // hid@w2 + b2
__device__ int   g_cnt[N_NODES];
__device__ int   g_off[N_NODES + 1];
__device__ int   g_cur[N_NODES];
__device__ int   g_csr[MAX_EDGES];

// ---------------- CSR build ----------------
__global__ void zero_cnt_kernel() {
    int i = blockIdx.x * blockDim.x + threadIdx.x;
    if (i < N_NODES) g_cnt[i] = 0;
}

__global__ void degree_kernel(const int* __restrict__ ei, int E) {
    int stride = gridDim.x * blockDim.x;
    for (int i = blockIdx.x * blockDim.x + threadIdx.x; i < E; i += stride)
        atomicAdd(&g_cnt[ei[i]], 1);
}

// single-block scan over 100k counts -> exclusive offsets (+ cursor copy)
__global__ void scan_kernel() {
    const int T = 1024;
    __shared__ int sums[T];
    int tid = threadIdx.x;
    const int chunk = (N_NODES + T - 1) / T;   // 98
    int start = tid * chunk;
    int end   = min(start + chunk, N_NODES);
    int s = 0;
    for (int i = start; i < end; i++) s += g_cnt[i];
    sums[tid] = s;
    __syncthreads();
    // Hillis-Steele inclusive scan
    for (int off = 1; off < T; off <<= 1) {
        int v = 0;
        if (tid >= off) v = sums[tid - off];
        __syncthreads();
        sums[tid] += v;
        __syncthreads();
    }
    int run = (tid > 0) ? sums[tid - 1] : 0;
    for (int i = start; i < end; i++) {
        g_off[i] = run;
        g_cur[i] = run;
        run += g_cnt[i];
    }
    if (tid == T - 1) g_off[N_NODES] = sums[T - 1];
}

__global__ void scatter_kernel(const int* __restrict__ ei, int E) {
    int stride = gridDim.x * blockDim.x;
    for (int i = blockIdx.x * blockDim.x + threadIdx.x; i < E; i += stride) {
        int r = ei[i];
        int c = ei[E + i];
        int pos = atomicAdd(&g_cur[r], 1);
        g_csr[pos] = c;
    }
}

// ---------------- GEMM: C[M,N] = A[M,K] @ W[K,N] + bias, fused epilogues ----------
// MODE 0: A = x (param), epilogue permutes cols into g_q/g_k/g_v (h,qkv,d split)
// MODE 1: A = g_xln,     epilogue relu -> g_hid
// MODE 2: A = g_hid,     epilogue plain -> g_f
template<int BM, int N_, int K_, int BK, int TM, int TN, int MODE>
__global__ __launch_bounds__(256)
void gemm_kernel(const float* __restrict__ A, const float* __restrict__ W,
                 const float* __restrict__ bias, int M)
{
    constexpr int TX = N_ / TN;
    constexpr int TY = BM / TM;
    static_assert(TX * TY == 256, "bad tile");
    static_assert((BM * BK) % 1024 == 0 && (BK * N_) % 1024 == 0, "bad loads");

    __shared__ float As[BK][BM];   // transposed: [k][m]
    __shared__ float Ws[BK][N_];

    const float* Ap = (MODE == 0) ? A : (MODE == 1 ? g_xln : g_hid);

    int tid = threadIdx.x;
    int ty = tid % TY;             // row index fastest within warp (smem-friendly)
    int tx = tid / TY;
    int m0 = blockIdx.x * BM;

    float acc[TM][TN];
#pragma unroll
    for (int i = 0; i < TM; i++)
#pragma unroll
        for (int j = 0; j < TN; j++) acc[i][j] = 0.f;

    for (int k0 = 0; k0 < K_; k0 += BK) {
        // load A tile (transposed into smem)
        constexpr int AF4 = BM * BK / 4 / 256;
#pragma unroll
        for (int t = 0; t < AF4; t++) {
            int f = tid + t * 256;
            int r  = f / (BK / 4);
            int kk = (f % (BK / 4)) * 4;
            float4 val = make_float4(0.f, 0.f, 0.f, 0.f);
            int row = m0 + r;
            if (row < M) val = *(const float4*)&Ap[(long long)row * K_ + k0 + kk];
            As[kk + 0][r] = val.x; As[kk + 1][r] = val.y;
            As[kk + 2][r] = val.z; As[kk + 3][r] = val.w;
        }
        // load W tile
        constexpr int WF4 = BK * N_ / 4 / 256;
#pragma unroll
        for (int t = 0; t < WF4; t++) {
            int f = tid + t * 256;
            int kk = f / (N_ / 4);
            int c  = (f % (N_ / 4)) * 4;
            *(float4*)&Ws[kk][c] = *(const float4*)&W[(long long)(k0 + kk) * N_ + c];
        }
        __syncthreads();

#pragma unroll
        for (int kk = 0; kk < BK; kk++) {
            float a[TM], w[TN];
#pragma unroll
            for (int i = 0; i < TM; i += 4)
                *(float4*)&a[i] = *(const float4*)&As[kk][ty * TM + i];
#pragma unroll
            for (int j = 0; j < TN; j += 4)
                *(float4*)&w[j] = *(const float4*)&Ws[kk][tx * TN + j];
#pragma unroll
            for (int i = 0; i < TM; i++)
#pragma unroll
                for (int j = 0; j < TN; j++)
                    acc[i][j] += a[i] * w[j];
        }
        __syncthreads();
    }

    // epilogue
#pragma unroll
    for (int i = 0; i < TM; i++) {
        int row = m0 + ty * TM + i;
        if (row >= M) continue;
        if (MODE == 0) {
#pragma unroll
            for (int j = 0; j < TN; j++) {
                int c = tx * TN + j;
                float val = acc[i][j] + bias[c];
                int h = c / 24, t = c % 24, r = t / 8, d = t % 8;
                int dst = row * EMBED + h * HD + d;
                if (r == 0)      g_q[dst] = val;
                else if (r == 1) g_k[dst] = val;
                else             g_v[dst] = val;
            }
        } else {
            float* Cp = (MODE == 1) ? g_hid : g_f;
#pragma unroll
            for (int j = 0; j < TN; j += 4) {
                int c = tx * TN + j;
                float4 v;
                v.x = acc[i][j + 0] + bias[c + 0];
                v.y = acc[i][j + 1] + bias[c + 1];
                v.z = acc[i][j + 2] + bias[c + 2];
                v.w = acc[i][j + 3] + bias[c + 3];
                if (MODE == 1) {
                    v.x = fmaxf(v.x, 0.f); v.y = fmaxf(v.y, 0.f);
                    v.z = fmaxf(v.z, 0.f); v.w = fmaxf(v.w, 0.f);
                }
                *(float4*)&Cp[(long long)row * N_ + c] = v;
            }
        }
    }
}

// ---------------- attention: warp per node, online softmax, fused res+LN1 -------
__global__ __launch_bounds__(256)
void attn_kernel(const float* __restrict__ x,
                 const float* __restrict__ ln1g, const float* __restrict__ ln1b)
{
    int w = (blockIdx.x * blockDim.x + threadIdx.x) >> 5;
    if (w >= N_NODES) return;
    int lane = threadIdx.x & 31;
    int base = w * 64 + lane * 2;          // lane covers elems 2*lane, 2*lane+1; head = lane/4

    float2 q = *(const float2*)&g_q[base];
    q.x *= 0.125f; q.y *= 0.125f;          // EMBED^-0.5

    float m = -1e30f, denom = 0.f, a0 = 0.f, a1 = 0.f;
    int s = g_off[w], e = g_off[w + 1];
    for (int j = s; j < e; j++) {
        int col = g_csr[j];
        float2 kk = *(const float2*)&g_k[col * 64 + lane * 2];
        float2 vv = *(const float2*)&g_v[col * 64 + lane * 2];
        float p = q.x * kk.x + q.y * kk.y;
        p += __shfl_xor_sync(0xffffffffu, p, 1);
        p += __shfl_xor_sync(0xffffffffu, p, 2);   // per-head dot, replicated in 4-lane group
        float nm   = fmaxf(m, p);
        float corr = __expf(m - nm);
        float wt   = __expf(p - nm);
        denom = denom * corr + wt;
        a0 = a0 * corr + wt * vv.x;
        a1 = a1 * corr + wt * vv.y;
        m = nm;
    }
    float inv = (e > s) ? (1.0f / denom) : 0.f;

    // residual + LayerNorm1 (over the 64-dim row held by the warp)
    float h0 = x[base] + a0 * inv;
    float h1 = x[base + 1] + a1 * inv;
    float ssum = h0 + h1;
#pragma unroll
    for (int o = 16; o > 0; o >>= 1) ssum += __shfl_xor_sync(0xffffffffu, ssum, o);
    float mean = ssum * (1.f / 64.f);
    float d0 = h0 - mean, d1 = h1 - mean;
    float vs = d0 * d0 + d1 * d1;
#pragma unroll
    for (int o = 16; o > 0; o >>= 1) vs += __shfl_xor_sync(0xffffffffu, vs, o);
    float r = rsqrtf(vs * (1.f / 64.f) + 1e-5f);
    int c = lane * 2;
    float2 out;
    out.x = d0 * r * ln1g[c]     + ln1b[c];
    out.y = d1 * r * ln1g[c + 1] + ln1b[c + 1];
    *(float2*)&g_xln[base] = out;
}

// ---------------- residual + LN2 -> output ----------------
__global__ __launch_bounds__(256)
void ln2_kernel(const float* __restrict__ ln2g, const float* __restrict__ ln2b,
                float* __restrict__ out)
{
    int w = (blockIdx.x * blockDim.x + threadIdx.x) >> 5;
    if (w >= N_NODES) return;
    int lane = threadIdx.x & 31;
    int base = w * 64 + lane * 2;
    float2 xa = *(const float2*)&g_xln[base];
    float2 fb = *(const float2*)&g_f[base];
    float h0 = xa.x + fb.x, h1 = xa.y + fb.y;
    float ssum = h0 + h1;
#pragma unroll
    for (int o = 16; o > 0; o >>= 1) ssum += __shfl_xor_sync(0xffffffffu, ssum, o);
    float mean = ssum * (1.f / 64.f);
    float d0 = h0 - mean, d1 = h1 - mean;
    float vs = d0 * d0 + d1 * d1;
#pragma unroll
    for (int o = 16; o > 0; o >>= 1) vs += __shfl_xor_sync(0xffffffffu, vs, o);
    float r = rsqrtf(vs * (1.f / 64.f) + 1e-5f);
    int c = lane * 2;
    float2 o2;
    o2.x = d0 * r * ln2g[c]     + ln2b[c];
    o2.y = d1 * r * ln2g[c + 1] + ln2b[c + 1];
    *(float2*)&out[base] = o2;
}

// ---------------- launcher ----------------
extern "C" void kernel_launch(void* const* d_in, const int* in_sizes, int n_in,
                              void* d_out, int out_size)
{
    const float* x      = (const float*)d_in[0];
    const int*   ei     = (const int*)d_in[1];      // JAX default: int64 downgraded to int32
    const float* attn_w = (const float*)d_in[2];
    const float* attn_b = (const float*)d_in[3];
    const float* w1     = (const float*)d_in[4];
    const float* b1     = (const float*)d_in[5];
    const float* w2     = (const float*)d_in[6];
    const float* b2     = (const float*)d_in[7];
    const float* ln1g   = (const float*)d_in[8];
    const float* ln1b   = (const float*)d_in[9];
    const float* ln2g   = (const float*)d_in[10];
    const float* ln2b   = (const float*)d_in[11];
    float* out = (float*)d_out;

    int M = in_sizes[0] / EMBED;       // 100000
    int E = in_sizes[1] / 2;           // 1600000

    // CSR build (int atomics only)
    zero_cnt_kernel<<<(N_NODES + 255) / 256, 256>>>();
    degree_kernel<<<2048, 256>>>(ei, E);
    scan_kernel<<<1, 1024>>>();
    scatter_kernel<<<2048, 256>>>(ei, E);

    // QKV projection (epilogue splits into q/k/v head-major)
    gemm_kernel<64, 192, 64, 32, 4, 12, 0><<<(M + 63) / 64, 256>>>(x, attn_w, attn_b, M);

    // sparse attention + residual + LN1
    int warps_blocks = (M * 32 + 255) / 256;
    attn_kernel<<<warps_blocks, 256>>>(x, ln1g, ln1b);

    // FFN
    gemm_kernel<64, 256, 64, 32, 4, 16, 1><<<(M + 63) / 64, 256>>>(nullptr, w1, b1, M);
    gemm_kernel<128, 64, 256, 32, 4, 8, 2><<<(M + 127) / 128, 256>>>(nullptr, w2, b2, M);

    // residual + LN2 -> output
    ln2_kernel<<<warps_blocks, 256>>>(ln2g, ln2b, out);
}

// round 6
// speedup vs baseline: 1.0110x; 1.0110x over previous
#include <cuda_runtime.h>

#define N_NODES   100000
#define EMBED     64
#define HEADS     8
#define HD        8
#define FFN_DIM   256
#define MAX_EDGES 1600000

typedef unsigned long long u64;

// packed dual-FMA: d = a*b + d on two fp32 lanes (FFMA2 in SASS; PTX-only form)
__device__ __forceinline__ float2 ffma2(float2 d, float2 a, float2 b) {
    u64 dd = *(u64*)&d, aa = *(u64*)&a, bb = *(u64*)&b;
    asm("fma.rn.f32x2 %0, %1, %2, %0;" : "+l"(dd) : "l"(aa), "l"(bb));
    return *(float2*)&dd;
}

// ---------------- scratch (device globals; no allocation allowed) ----------------
__device__ float g_q[N_NODES * EMBED];
__device__ float g_k[N_NODES * EMBED];
__device__ float g_v[N_NODES * EMBED];
__device__ float g_xln[N_NODES * EMBED];     // LN1(x + attn)
__device__ float g_hid[N_NODES * FFN_DIM];   // relu(xln@w1+b1)
__device__ float g_f[N_NODES * EMBED];       // hid@w2 + b2
__device__ int   g_cnt[N_NODES];
__device__ int   g_off[N_NODES + 1];
__device__ int   g_cur[N_NODES];
__device__ int   g_csr[MAX_EDGES];

// ---------------- CSR build ----------------
__global__ void zero_cnt_kernel() {
    int i = blockIdx.x * blockDim.x + threadIdx.x;
    if (i < N_NODES) g_cnt[i] = 0;
}

__global__ void degree_kernel(const int* __restrict__ ei, int E) {
    int stride = gridDim.x * blockDim.x;
    for (int i = blockIdx.x * blockDim.x + threadIdx.x; i < E; i += stride)
        atomicAdd(&g_cnt[ei[i]], 1);
}

// single-block scan over 100k counts -> exclusive offsets (+ cursor copy)
__global__ void scan_kernel() {
    const int T = 1024;
    __shared__ int sums[T];
    int tid = threadIdx.x;
    const int chunk = (N_NODES + T - 1) / T;   // 98
    int start = tid * chunk;
    int end   = min(start + chunk, N_NODES);
    int s = 0;
    for (int i = start; i < end; i++) s += g_cnt[i];
    sums[tid] = s;
    __syncthreads();
    for (int off = 1; off < T; off <<= 1) {
        int v = 0;
        if (tid >= off) v = sums[tid - off];
        __syncthreads();
        sums[tid] += v;
        __syncthreads();
    }
    int run = (tid > 0) ? sums[tid - 1] : 0;
    for (int i = start; i < end; i++) {
        g_off[i] = run;
        g_cur[i] = run;
        run += g_cnt[i];
    }
    if (tid == T - 1) g_off[N_NODES] = sums[T - 1];
}

__global__ void scatter_kernel(const int* __restrict__ ei, int E) {
    int stride = gridDim.x * blockDim.x;
    for (int i = blockIdx.x * blockDim.x + threadIdx.x; i < E; i += stride) {
        int r = ei[i];
        int c = ei[E + i];
        int pos = atomicAdd(&g_cur[r], 1);
        g_csr[pos] = c;
    }
}

// ---------------- GEMM: C[M,N] = A[M,K] @ W[K,N] + bias, fused epilogues ----------
// MODE 0: A = x (param), epilogue permutes cols into g_q/g_k/g_v (h,qkv,d split)
// MODE 1: A = g_xln,     epilogue relu -> g_hid
// MODE 2: A = g_hid,     epilogue plain -> g_f
template<int BM, int N_, int K_, int BK, int TM, int TN, int MODE>
__global__ __launch_bounds__(256)
void gemm_kernel(const float* __restrict__ A, const float* __restrict__ W,
                 const float* __restrict__ bias, int M)
{
    constexpr int TX = N_ / TN;
    constexpr int TY = BM / TM;
    constexpr int TN2 = TN / 2;
    static_assert(TX * TY == 256, "bad tile");
    static_assert((BM * BK) % 1024 == 0 && (BK * N_) % 1024 == 0, "bad loads");
    static_assert(TN % 4 == 0 && TM % 4 == 0, "vec");

    __shared__ float As[BK][BM];   // transposed: [k][m]
    __shared__ float Ws[BK][N_];

    const float* Ap = (MODE == 0) ? A : (MODE == 1 ? g_xln : g_hid);

    int tid = threadIdx.x;
    int ty = tid % TY;             // row index fastest within warp (smem-friendly)
    int tx = tid / TY;
    int m0 = blockIdx.x * BM;

    float2 acc[TM][TN2];
#pragma unroll
    for (int i = 0; i < TM; i++)
#pragma unroll
        for (int j = 0; j < TN2; j++) acc[i][j] = make_float2(0.f, 0.f);

    for (int k0 = 0; k0 < K_; k0 += BK) {
        constexpr int AF4 = BM * BK / 4 / 256;
#pragma unroll
        for (int t = 0; t < AF4; t++) {
            int f = tid + t * 256;
            int r  = f / (BK / 4);
            int kk = (f % (BK / 4)) * 4;
            float4 val = make_float4(0.f, 0.f, 0.f, 0.f);
            int row = m0 + r;
            if (row < M) val = *(const float4*)&Ap[(long long)row * K_ + k0 + kk];
            As[kk + 0][r] = val.x; As[kk + 1][r] = val.y;
            As[kk + 2][r] = val.z; As[kk + 3][r] = val.w;
        }
        constexpr int WF4 = BK * N_ / 4 / 256;
#pragma unroll
        for (int t = 0; t < WF4; t++) {
            int f = tid + t * 256;
            int kk = f / (N_ / 4);
            int c  = (f % (N_ / 4)) * 4;
            *(float4*)&Ws[kk][c] = *(const float4*)&W[(long long)(k0 + kk) * N_ + c];
        }
        __syncthreads();

#pragma unroll
        for (int kk = 0; kk < BK; kk++) {
            float a[TM]; float2 w[TN2];
#pragma unroll
            for (int i = 0; i < TM; i += 4)
                *(float4*)&a[i] = *(const float4*)&As[kk][ty * TM + i];
#pragma unroll
            for (int j = 0; j < TN2; j += 2)
                *(float4*)&w[j] = *(const float4*)&Ws[kk][tx * TN + j * 2];
#pragma unroll
            for (int i = 0; i < TM; i++) {
                float2 ap = make_float2(a[i], a[i]);
#pragma unroll
                for (int j = 0; j < TN2; j++)
                    acc[i][j] = ffma2(acc[i][j], ap, w[j]);
            }
        }
        __syncthreads();
    }

    // epilogue
#pragma unroll
    for (int i = 0; i < TM; i++) {
        int row = m0 + ty * TM + i;
        if (row >= M) continue;
        if (MODE == 0) {
#pragma unroll
            for (int j = 0; j < TN; j++) {
                int c = tx * TN + j;
                float av = (j & 1) ? acc[i][j / 2].y : acc[i][j / 2].x;
                float val = av + bias[c];
                int h = c / 24, t = c % 24, r = t / 8, d = t % 8;
                int dst = row * EMBED + h * HD + d;
                if (r == 0)      g_q[dst] = val;
                else if (r == 1) g_k[dst] = val;
                else             g_v[dst] = val;
            }
        } else {
            float* Cp = (MODE == 1) ? g_hid : g_f;
#pragma unroll
            for (int j = 0; j < TN; j += 4) {
                int c = tx * TN + j;
                float4 v;
                v.x = acc[i][j / 2].x     + bias[c + 0];
                v.y = acc[i][j / 2].y     + bias[c + 1];
                v.z = acc[i][j / 2 + 1].x + bias[c + 2];
                v.w = acc[i][j / 2 + 1].y + bias[c + 3];
                if (MODE == 1) {
                    v.x = fmaxf(v.x, 0.f); v.y = fmaxf(v.y, 0.f);
                    v.z = fmaxf(v.z, 0.f); v.w = fmaxf(v.w, 0.f);
                }
                *(float4*)&Cp[(long long)row * N_ + c] = v;
            }
        }
    }
}

// ---------------- attention: warp per node, online softmax, fused res+LN1 -------
// one-deep software pipeline on the gathered K/V rows to hide L2 latency
__global__ __launch_bounds__(256)
void attn_kernel(const float* __restrict__ x,
                 const float* __restrict__ ln1g, const float* __restrict__ ln1b)
{
    int w = (blockIdx.x * blockDim.x + threadIdx.x) >> 5;
    if (w >= N_NODES) return;
    int lane = threadIdx.x & 31;
    int base = w * 64 + lane * 2;          // lane covers elems 2*lane, 2*lane+1; head = lane/4

    float2 q = *(const float2*)&g_q[base];
    q.x *= 0.125f; q.y *= 0.125f;          // EMBED^-0.5

    float m = -1e30f, denom = 0.f, a0 = 0.f, a1 = 0.f;
    int s = g_off[w], e = g_off[w + 1];

    float2 kk = make_float2(0.f, 0.f), vv = make_float2(0.f, 0.f);
    if (s < e) {
        int col = g_csr[s];
        kk = *(const float2*)&g_k[col * 64 + lane * 2];
        vv = *(const float2*)&g_v[col * 64 + lane * 2];
    }
    for (int j = s; j < e; j++) {
        float2 ck = kk, cv = vv;
        if (j + 1 < e) {                   // prefetch next edge's rows
            int nc = g_csr[j + 1];
            kk = *(const float2*)&g_k[nc * 64 + lane * 2];
            vv = *(const float2*)&g_v[nc * 64 + lane * 2];
        }
        float p = q.x * ck.x + q.y * ck.y;
        p += __shfl_xor_sync(0xffffffffu, p, 1);
        p += __shfl_xor_sync(0xffffffffu, p, 2);   // per-head dot, replicated in 4-lane group
        float nm   = fmaxf(m, p);
        float corr = __expf(m - nm);
        float wt   = __expf(p - nm);
        denom = denom * corr + wt;
        a0 = a0 * corr + wt * cv.x;
        a1 = a1 * corr + wt * cv.y;
        m = nm;
    }
    float inv = (e > s) ? (1.0f / denom) : 0.f;

    // residual + LayerNorm1 (over the 64-dim row held by the warp)
    float h0 = x[base] + a0 * inv;
    float h1 = x[base + 1] + a1 * inv;
    float ssum = h0 + h1;
#pragma unroll
    for (int o = 16; o > 0; o >>= 1) ssum += __shfl_xor_sync(0xffffffffu, ssum, o);
    float mean = ssum * (1.f / 64.f);
    float d0 = h0 - mean, d1 = h1 - mean;
    float vs = d0 * d0 + d1 * d1;
#pragma unroll
    for (int o = 16; o > 0; o >>= 1) vs += __shfl_xor_sync(0xffffffffu, vs, o);
    float r = rsqrtf(vs * (1.f / 64.f) + 1e-5f);
    int c = lane * 2;
    float2 out;
    out.x = d0 * r * ln1g[c]     + ln1b[c];
    out.y = d1 * r * ln1g[c + 1] + ln1b[c + 1];
    *(float2*)&g_xln[base] = out;
}

// ---------------- residual + LN2 -> output ----------------
__global__ __launch_bounds__(256)
void ln2_kernel(const float* __restrict__ ln2g, const float* __restrict__ ln2b,
                float* __restrict__ out)
{
    int w = (blockIdx.x * blockDim.x + threadIdx.x) >> 5;
    if (w >= N_NODES) return;
    int lane = threadIdx.x & 31;
    int base = w * 64 + lane * 2;
    float2 xa = *(const float2*)&g_xln[base];
    float2 fb = *(const float2*)&g_f[base];
    float h0 = xa.x + fb.x, h1 = xa.y + fb.y;
    float ssum = h0 + h1;
#pragma unroll
    for (int o = 16; o > 0; o >>= 1) ssum += __shfl_xor_sync(0xffffffffu, ssum, o);
    float mean = ssum * (1.f / 64.f);
    float d0 = h0 - mean, d1 = h1 - mean;
    float vs = d0 * d0 + d1 * d1;
#pragma unroll
    for (int o = 16; o > 0; o >>= 1) vs += __shfl_xor_sync(0xffffffffu, vs, o);
    float r = rsqrtf(vs * (1.f / 64.f) + 1e-5f);
    int c = lane * 2;
    float2 o2;
    o2.x = d0 * r * ln2g[c]     + ln2b[c];
    o2.y = d1 * r * ln2g[c + 1] + ln2b[c + 1];
    *(float2*)&out[base] = o2;
}

// ---------------- launcher ----------------
extern "C" void kernel_launch(void* const* d_in, const int* in_sizes, int n_in,
                              void* d_out, int out_size)
{
    const float* x      = (const float*)d_in[0];
    const int*   ei     = (const int*)d_in[1];      // int32 on device (JAX x64 off)
    const float* attn_w = (const float*)d_in[2];
    const float* attn_b = (const float*)d_in[3];
    const float* w1     = (const float*)d_in[4];
    const float* b1     = (const float*)d_in[5];
    const float* w2     = (const float*)d_in[6];
    const float* b2     = (const float*)d_in[7];
    const float* ln1g   = (const float*)d_in[8];
    const float* ln1b   = (const float*)d_in[9];
    const float* ln2g   = (const float*)d_in[10];
    const float* ln2b   = (const float*)d_in[11];
    float* out = (float*)d_out;

    int M = in_sizes[0] / EMBED;       // 100000
    int E = in_sizes[1] / 2;           // 1600000

    // CSR build (int atomics only)
    zero_cnt_kernel<<<(N_NODES + 255) / 256, 256>>>();
    degree_kernel<<<2048, 256>>>(ei, E);
    scan_kernel<<<1, 1024>>>();
    scatter_kernel<<<2048, 256>>>(ei, E);

    // QKV projection (epilogue splits into q/k/v head-major)
    gemm_kernel<64, 192, 64, 32, 4, 12, 0><<<(M + 63) / 64, 256>>>(x, attn_w, attn_b, M);

    // sparse attention + residual + LN1
    int warps_blocks = (M * 32 + 255) / 256;
    attn_kernel<<<warps_blocks, 256>>>(x, ln1g, ln1b);

    // FFN
    gemm_kernel<64, 256, 64, 32, 4, 16, 1><<<(M + 63) / 64, 256>>>(nullptr, w1, b1, M);
    gemm_kernel<128, 64, 256, 64, 4, 8, 2><<<(M + 127) / 128, 256>>>(nullptr, w2, b2, M);

    // residual + LN2 -> output
    ln2_kernel<<<warps_blocks, 256>>>(ln2g, ln2b, out);
}